// round 8
// baseline (speedup 1.0000x reference)
#include <cuda_runtime.h>
#include <cuda_bf16.h>

#define BB 8
#define NN 2048
#define BIGF 1e30f

// z-bucketing
#define NB   64
#define ZLO  (-6.0f)
#define ZHI  (6.0f)
#define ZW   ((ZHI - ZLO) / NB)          // 0.1875
#define ZINV (NB / (ZHI - ZLO))

// chamfer shape: warp = 32 queries; block = 4 warps; grid (16, 16)
#define GZT      16                      // tasks (dir, b)
#define CHB      16                      // blockIdx.x extent
#define MAXCHUNK 64                      // 2048/32
#define NBLK     (CHB * GZT)             // 256

// Scratch (allocation-free). Points stored transformed: (x+y, x-y, z, 0),
// bucket-sorted by z. g_valid[0]=clean(points+target), g_valid[1]=predp(points+pred)
__device__ __align__(16) float4 g_valid[2][BB][NN];
__device__ int          g_S[2][BB][NB + 1];     // bucket starts, S[NB]=cnt
__device__ int          g_cnt[BB];
__device__ float        g_l1part[BB];
__device__ float        g_warpsum[GZT][MAXCHUNK];
__device__ unsigned int g_done;                  // zero at load; reset by last block

// ---------------------------------------------------------------------------
// Kernel 1: prep — 16 blocks (set s, batch b) x 1024 threads, 2 points/thread.
// Counting-sort valid points into z-buckets; l1 partial (s==0 only).
// ---------------------------------------------------------------------------
__global__ void __launch_bounds__(1024)
prep_kernel(const float* __restrict__ pred,
            const float* __restrict__ target,
            const int*   __restrict__ mask,
            const float* __restrict__ points) {
    int s = blockIdx.x & 1, b = blockIdx.x >> 1;
    int tid = threadIdx.x;

    __shared__ int   hist[NB];
    __shared__ int   bstart[NB + 1];
    __shared__ int   cursor[NB];
    __shared__ float wred[32];

    if (tid < NB) hist[tid] = 0;
    __syncthreads();

    float u[2], v[2], z[2];
    int   valid[2], bk[2];
    float l1 = 0.f;
#pragma unroll
    for (int it = 0; it < 2; ++it) {
        int n  = tid + it * 1024;
        int gi = b * NN + n;
        const float* xx = points + gi * 3;
        const float* aa = (s ? pred : target) + gi * 3;
        float a0 = aa[0], a1 = aa[1], a2 = aa[2];
        float x0 = xx[0], x1 = xx[1], x2 = xx[2];
        valid[it] = mask[gi];
        float P0 = x0 + a0, P1 = x1 + a1, P2 = x2 + a2;
        u[it] = P0 + P1; v[it] = P0 - P1; z[it] = P2;
        bk[it] = 0;
        if (valid[it]) {
            int k = (int)floorf((P2 - ZLO) * ZINV);
            k = max(0, min(NB - 1, k));
            bk[it] = k;
            atomicAdd(&hist[k], 1);
            if (s == 0) {
                const float* pp = pred + gi * 3;
                l1 += fabsf(pp[0] - a0) + fabsf(pp[1] - a1) + fabsf(pp[2] - a2);
            }
        }
    }
    __syncthreads();

    if (tid == 0) {                      // serial 64-way prefix, trivial
        int acc = 0;
#pragma unroll
        for (int k = 0; k < NB; ++k) { bstart[k] = acc; acc += hist[k]; }
        bstart[NB] = acc;
    }
    __syncthreads();
    if (tid < NB)  cursor[tid] = bstart[tid];
    if (tid <= NB) g_S[s][b][tid] = bstart[tid];
    if (s == 0 && tid == 0) g_cnt[b] = bstart[NB];
    __syncthreads();

#pragma unroll
    for (int it = 0; it < 2; ++it)
        if (valid[it]) {
            int pos = atomicAdd(&cursor[bk[it]], 1);
            g_valid[s][b][pos] = make_float4(u[it], v[it], z[it], 0.f);
        }

    if (s == 0) {                        // deterministic l1 block reduction
#pragma unroll
        for (int o = 16; o > 0; o >>= 1) l1 += __shfl_xor_sync(0xffffffffu, l1, o);
        if ((tid & 31) == 0) wred[tid >> 5] = l1;
        __syncthreads();
        if (tid == 0) {
            float t = 0.f;
#pragma unroll
            for (int i = 0; i < 32; ++i) t += wred[i];
            g_l1part[b] = t;
        }
    }
}

// ---------------------------------------------------------------------------
// Ref scan: uniform LDG.128 broadcast, unroll 8, dual-min accumulators.
// |dx|+|dy|+|dz| == max(|du|,|dv|) + |dz| with (u,v) = (x+y, x-y).
// ---------------------------------------------------------------------------
__device__ __forceinline__ void scan_refs(const float4* __restrict__ R,
                                          int j0, int j1,
                                          float qx, float qy, float qz,
                                          float& mn0, float& mn1) {
    int j = j0;
    for (; j + 8 <= j1; j += 8) {
        float4 y0 = R[j+0], y1 = R[j+1], y2 = R[j+2], y3 = R[j+3];
        float4 y4 = R[j+4], y5 = R[j+5], y6 = R[j+6], y7 = R[j+7];
        float d0 = fmaxf(fabsf(qx-y0.x), fabsf(qy-y0.y)) + fabsf(qz-y0.z);
        float d1 = fmaxf(fabsf(qx-y1.x), fabsf(qy-y1.y)) + fabsf(qz-y1.z);
        float d2 = fmaxf(fabsf(qx-y2.x), fabsf(qy-y2.y)) + fabsf(qz-y2.z);
        float d3 = fmaxf(fabsf(qx-y3.x), fabsf(qy-y3.y)) + fabsf(qz-y3.z);
        float d4 = fmaxf(fabsf(qx-y4.x), fabsf(qy-y4.y)) + fabsf(qz-y4.z);
        float d5 = fmaxf(fabsf(qx-y5.x), fabsf(qy-y5.y)) + fabsf(qz-y5.z);
        float d6 = fmaxf(fabsf(qx-y6.x), fabsf(qy-y6.y)) + fabsf(qz-y6.z);
        float d7 = fmaxf(fabsf(qx-y7.x), fabsf(qy-y7.y)) + fabsf(qz-y7.z);
        mn0 = fminf(mn0, fminf(fminf(d0, d2), fminf(d4, d6)));
        mn1 = fminf(mn1, fminf(fminf(d1, d3), fminf(d5, d7)));
    }
    for (; j < j1; ++j) {
        float4 y = R[j];
        float d = fmaxf(fabsf(qx-y.x), fabsf(qy-y.y)) + fabsf(qz-y.z);
        mn0 = fminf(mn0, d);
    }
}

__device__ __forceinline__ float warp_max(float v) {
#pragma unroll
    for (int o = 16; o > 0; o >>= 1) v = fmaxf(v, __shfl_xor_sync(0xffffffffu, v, o));
    return v;
}

// ---------------------------------------------------------------------------
// Kernel 2: chamfer with z-window pruning. Each warp owns 32 sorted queries;
// expands ref buckets outward from its z-span, stops when gap >= warp bound U.
// ---------------------------------------------------------------------------
__global__ void __launch_bounds__(128)
chamfer_kernel(float* __restrict__ out) {
    int task = blockIdx.y;
    int b    = task >> 1;
    int dir  = task & 1;                 // 0: clean->pred, 1: pred->clean
    int cnt  = g_cnt[b];
    int w    = threadIdx.x >> 5, lane = threadIdx.x & 31;
    int chunk = blockIdx.x * 4 + w;      // 0..63
    int q     = chunk * 32 + lane;
    bool active = q < cnt;
    unsigned amask = __ballot_sync(0xffffffffu, active);

    if (amask != 0u) {
        const float4* __restrict__ Q = g_valid[dir][b];
        const float4* __restrict__ R = g_valid[dir ^ 1][b];
        const int*    __restrict__ S = g_S[dir ^ 1][b];

        float4 vq = Q[active ? q : (cnt - 1)];
        float qx = vq.x, qy = vq.y, qz = vq.z;
        float mn0 = BIGF, mn1 = BIGF;

        // warp z-span over active lanes
        float zl = active ? qz : BIGF, zh = active ? qz : -BIGF;
#pragma unroll
        for (int o = 16; o > 0; o >>= 1) {
            zl = fminf(zl, __shfl_xor_sync(0xffffffffu, zl, o));
            zh = fmaxf(zh, __shfl_xor_sync(0xffffffffu, zh, o));
        }
        int klo = max(0, min(NB - 1, (int)floorf((zl - ZLO) * ZINV)));
        int khi = max(0, min(NB - 1, (int)floorf((zh - ZLO) * ZINV)));

        // initial span (contiguous refs), then expand outward with pruning
        scan_refs(R, S[klo], S[khi + 1], qx, qy, qz, mn0, mn1);
        float U = warp_max(active ? fminf(mn0, mn1) : 0.f);

        int kl = klo - 1, kr = khi + 1;
        while (1) {
            if (kl < 0 && kr >= NB) break;
            float gl = (kl >= 0) ? (zl - (ZLO + (kl + 1) * ZW)) : BIGF;
            float gr = (kr < NB) ? ((ZLO + kr * ZW) - zh)       : BIGF;
            float g  = fminf(gl, gr);
            if (g > U + 1e-4f) break;    // |dz| alone already exceeds every lane's min
            int k;
            if (gl <= gr) { k = kl; --kl; } else { k = kr; ++kr; }
            scan_refs(R, S[k], S[k + 1], qx, qy, qz, mn0, mn1);
            U = warp_max(active ? fminf(mn0, mn1) : 0.f);
        }

        float sv = active ? fminf(mn0, mn1) : 0.f;
#pragma unroll
        for (int o = 16; o > 0; o >>= 1) sv += __shfl_xor_sync(0xffffffffu, sv, o);
        if (lane == 0) g_warpsum[task][chunk] = sv;
    } else {
        if (lane == 0) g_warpsum[task][chunk] = 0.f;
    }

    // -------- arrive; last block finalizes --------
    __threadfence();
    __syncthreads();
    __shared__ int is_last;
    int tid = threadIdx.x;
    if (tid == 0)
        is_last = (atomicAdd(&g_done, 1u) == NBLK - 1);
    __syncthreads();
    if (!is_last) return;
    __threadfence();

    __shared__ float ts[GZT];
    if (tid < GZT) {
        float sum = 0.f;
#pragma unroll
        for (int c = 0; c < MAXCHUNK; ++c) sum += g_warpsum[tid][c];
        ts[tid] = sum / (float)g_cnt[tid >> 1];
    }
    __syncthreads();
    if (tid == 0) {
        float cdsum = 0.f;
#pragma unroll
        for (int t = 0; t < GZT; ++t) cdsum += ts[t];
        float l1num = 0.f; int msum = 0;
#pragma unroll
        for (int bb = 0; bb < BB; ++bb) { l1num += g_l1part[bb]; msum += g_cnt[bb]; }
        float l1 = l1num / 3.0f / (float)msum;
        float cd = cdsum / (float)BB;
        out[0] = l1 + expf(-l1) * cd;
        g_done = 0;                      // reset for next graph replay
    }
}

// ---------------------------------------------------------------------------
extern "C" void kernel_launch(void* const* d_in, const int* in_sizes, int n_in,
                              void* d_out, int out_size) {
    const float* pred   = (const float*)d_in[0];
    const float* target = (const float*)d_in[1];
    const int*   mask   = (const int*)  d_in[2];
    const float* points = (const float*)d_in[3];
    float* out = (float*)d_out;

    prep_kernel<<<16, 1024>>>(pred, target, mask, points);

    dim3 grid(CHB, GZT);                 // (16, 16) = 256 blocks
    chamfer_kernel<<<grid, 128>>>(out);
}

// round 9
// speedup vs baseline: 1.3753x; 1.3753x over previous
#include <cuda_runtime.h>
#include <cuda_bf16.h>

#define BB 8
#define NN 2048
#define BIGF 1e30f

// z-bucketing
#define NB   64
#define ZLO  (-6.0f)
#define ZHI  (6.0f)
#define ZINV (NB / (ZHI - ZLO))

// chamfer shape: block = 256 thr = 8 warps; warp = 16 queries x 2 lanes
#define QPB  128                  // queries per block
#define QPW  16                   // queries per warp
#define WPB  8                    // warps per block
#define CHQ  (NN / QPB)           // 16 query chunks
#define GZT  16                   // tasks (dir, b)
#define NBLK (CHQ * GZT)          // 256 blocks

// Scratch (allocation-free). Points transformed: (x+y, x-y, z, 0), z-sorted.
// g_valid[0]=clean(points+target), g_valid[1]=predp(points+pred)
__device__ __align__(16) float4 g_valid[2][BB][NN];
__device__ int          g_S[2][BB][NB + 1];   // bucket starts, S[NB]=cnt
__device__ int          g_cnt[BB];
__device__ float        g_l1part[BB];
__device__ float        g_warpsum[GZT][CHQ * WPB];
__device__ unsigned int g_done;               // zero at load; reset by last block

// ---------------------------------------------------------------------------
// Kernel 1: prep — 16 blocks (set s, batch b) x 1024 threads, 2 points/thread.
// Counting-sort valid points into z-buckets; l1 partial (s==0 only).
// ---------------------------------------------------------------------------
__global__ void __launch_bounds__(1024)
prep_kernel(const float* __restrict__ pred,
            const float* __restrict__ target,
            const int*   __restrict__ mask,
            const float* __restrict__ points) {
    int s = blockIdx.x & 1, b = blockIdx.x >> 1;
    int tid = threadIdx.x;

    __shared__ int   hist[NB];
    __shared__ int   bstart[NB + 1];
    __shared__ int   cursor[NB];
    __shared__ float wred[32];

    if (tid < NB) hist[tid] = 0;
    __syncthreads();

    float u[2], v[2], z[2];
    int   valid[2], bk[2];
    float l1 = 0.f;
#pragma unroll
    for (int it = 0; it < 2; ++it) {
        int n  = tid + it * 1024;
        int gi = b * NN + n;
        const float* xx = points + gi * 3;
        const float* aa = (s ? pred : target) + gi * 3;
        float a0 = aa[0], a1 = aa[1], a2 = aa[2];
        float x0 = xx[0], x1 = xx[1], x2 = xx[2];
        valid[it] = mask[gi];
        float P0 = x0 + a0, P1 = x1 + a1, P2 = x2 + a2;
        u[it] = P0 + P1; v[it] = P0 - P1; z[it] = P2;
        bk[it] = 0;
        if (valid[it]) {
            int k = (int)floorf((P2 - ZLO) * ZINV);
            k = max(0, min(NB - 1, k));
            bk[it] = k;
            atomicAdd(&hist[k], 1);
            if (s == 0) {
                const float* pp = pred + gi * 3;
                l1 += fabsf(pp[0] - a0) + fabsf(pp[1] - a1) + fabsf(pp[2] - a2);
            }
        }
    }
    __syncthreads();

    if (tid == 0) {
        int acc = 0;
#pragma unroll
        for (int k = 0; k < NB; ++k) { bstart[k] = acc; acc += hist[k]; }
        bstart[NB] = acc;
    }
    __syncthreads();
    if (tid < NB)  cursor[tid] = bstart[tid];
    if (tid <= NB) g_S[s][b][tid] = bstart[tid];
    if (s == 0 && tid == 0) g_cnt[b] = bstart[NB];
    __syncthreads();

#pragma unroll
    for (int it = 0; it < 2; ++it)
        if (valid[it]) {
            int pos = atomicAdd(&cursor[bk[it]], 1);
            g_valid[s][b][pos] = make_float4(u[it], v[it], z[it], 0.f);
        }

    if (s == 0) {
#pragma unroll
        for (int o = 16; o > 0; o >>= 1) l1 += __shfl_xor_sync(0xffffffffu, l1, o);
        if ((tid & 31) == 0) wred[tid >> 5] = l1;
        __syncthreads();
        if (tid == 0) {
            float t = 0.f;
#pragma unroll
            for (int i = 0; i < 32; ++i) t += wred[i];
            g_l1part[b] = t;
        }
    }
}

// ---------------------------------------------------------------------------
// Ref scan: unroll 8, dual-min accumulators. All 16 lanes of a half share j.
// |dx|+|dy|+|dz| == max(|du|,|dv|) + |dz| with (u,v) = (x+y, x-y).
// ---------------------------------------------------------------------------
__device__ __forceinline__ void scan_refs(const float4* __restrict__ R,
                                          int j0, int j1,
                                          float qx, float qy, float qz,
                                          float& mn0, float& mn1) {
    int j = j0;
    for (; j + 8 <= j1; j += 8) {
        float4 y0 = R[j+0], y1 = R[j+1], y2 = R[j+2], y3 = R[j+3];
        float4 y4 = R[j+4], y5 = R[j+5], y6 = R[j+6], y7 = R[j+7];
        float d0 = fmaxf(fabsf(qx-y0.x), fabsf(qy-y0.y)) + fabsf(qz-y0.z);
        float d1 = fmaxf(fabsf(qx-y1.x), fabsf(qy-y1.y)) + fabsf(qz-y1.z);
        float d2 = fmaxf(fabsf(qx-y2.x), fabsf(qy-y2.y)) + fabsf(qz-y2.z);
        float d3 = fmaxf(fabsf(qx-y3.x), fabsf(qy-y3.y)) + fabsf(qz-y3.z);
        float d4 = fmaxf(fabsf(qx-y4.x), fabsf(qy-y4.y)) + fabsf(qz-y4.z);
        float d5 = fmaxf(fabsf(qx-y5.x), fabsf(qy-y5.y)) + fabsf(qz-y5.z);
        float d6 = fmaxf(fabsf(qx-y6.x), fabsf(qy-y6.y)) + fabsf(qz-y6.z);
        float d7 = fmaxf(fabsf(qx-y7.x), fabsf(qy-y7.y)) + fabsf(qz-y7.z);
        mn0 = fminf(mn0, fminf(fminf(d0, d2), fminf(d4, d6)));
        mn1 = fminf(mn1, fminf(fminf(d1, d3), fminf(d5, d7)));
    }
    for (; j < j1; ++j) {
        float4 y = R[j];
        float d = fmaxf(fabsf(qx-y.x), fabsf(qy-y.y)) + fabsf(qz-y.z);
        mn0 = fminf(mn0, d);
    }
}

// ---------------------------------------------------------------------------
// Kernel 2: two-phase pruned chamfer. Warp = 16 queries x 2 lanes.
// ---------------------------------------------------------------------------
__global__ void __launch_bounds__(256)
chamfer_kernel(float* __restrict__ out) {
    int task = blockIdx.y;
    int b    = task >> 1;
    int dir  = task & 1;
    int cnt  = g_cnt[b];
    int tid  = threadIdx.x;
    int w    = tid >> 5, lane = tid & 31;
    int half = lane >> 4;
    int q    = blockIdx.x * QPB + w * QPW + (lane & 15);
    bool active = q < cnt;

    float warpres = 0.f;
    if (blockIdx.x * QPB + w * QPW < cnt) {           // warp has work
        const float4* __restrict__ Q = g_valid[dir][b];
        const float4* __restrict__ R = g_valid[dir ^ 1][b];
        const int*    __restrict__ S = g_S[dir ^ 1][b];

        float4 vq = Q[active ? q : 0];
        float qx = vq.x, qy = vq.y, qz = vq.z;

        // warp z-span over active lanes
        float zl = active ? qz : BIGF, zh = active ? qz : -BIGF;
#pragma unroll
        for (int o = 16; o > 0; o >>= 1) {
            zl = fminf(zl, __shfl_xor_sync(0xffffffffu, zl, o));
            zh = fmaxf(zh, __shfl_xor_sync(0xffffffffu, zh, o));
        }

        // Phase A: 64-ref window centered on span (uniform per half)
        int kc = max(0, min(NB - 1, (int)floorf(((zl + zh) * 0.5f - ZLO) * ZINV)));
        int j0 = S[kc] - 32;
        j0 = max(0, min(j0, max(cnt - 64, 0)));
        float mn0 = BIGF, mn1 = BIGF;
        int a0 = min(j0 + half * 32, cnt);
        int a1 = min(a0 + 32, cnt);
        scan_refs(R, a0, a1, qx, qy, qz, mn0, mn1);
        float mA = fminf(mn0, mn1);
        mA = fminf(mA, __shfl_xor_sync(0xffffffffu, mA, 16));   // combine halves
        float U = active ? mA : 0.f;
#pragma unroll
        for (int o = 16; o > 0; o >>= 1)
            U = fmaxf(U, __shfl_xor_sync(0xffffffffu, U, o));

        // Phase B: one contiguous window [zl-U, zh+U] (margin for fp safety)
        float Um = U * 1.0001f + 1e-5f;
        int klo = max(0, min(NB - 1, (int)floorf((zl - Um - ZLO) * ZINV)));
        int khi = max(0, min(NB - 1, (int)floorf((zh + Um - ZLO) * ZINV)));
        int lo = S[klo], hi = S[khi + 1];
        int mid = (lo + hi) >> 1;
        int b0 = half ? mid : lo;
        int b1 = half ? hi  : mid;
        scan_refs(R, b0, b1, qx, qy, qz, mn0, mn1);

        float m = fminf(mn0, mn1);
        m = fminf(m, __shfl_xor_sync(0xffffffffu, m, 16));      // both halves

        float sv = (active && half == 0) ? m : 0.f;             // count each q once
#pragma unroll
        for (int o = 16; o > 0; o >>= 1) sv += __shfl_xor_sync(0xffffffffu, sv, o);
        warpres = sv;
    }
    if (lane == 0) g_warpsum[task][blockIdx.x * WPB + w] = warpres;

    // -------- arrive; last block finalizes --------
    __threadfence();
    __syncthreads();
    __shared__ int is_last;
    if (tid == 0)
        is_last = (atomicAdd(&g_done, 1u) == NBLK - 1);
    __syncthreads();
    if (!is_last) return;
    __threadfence();

    // 8 warps; warp w reduces tasks w and w+8 (128 slots each, 4/lane)
    __shared__ float ts[GZT];
    int lane2 = tid & 31, w2 = tid >> 5;
#pragma unroll
    for (int rep = 0; rep < 2; ++rep) {
        int t = w2 + rep * 8;
        float s = 0.f;
#pragma unroll
        for (int c = 0; c < 4; ++c) s += g_warpsum[t][lane2 * 4 + c];
#pragma unroll
        for (int o = 16; o > 0; o >>= 1) s += __shfl_xor_sync(0xffffffffu, s, o);
        if (lane2 == 0) ts[t] = s / (float)g_cnt[t >> 1];
    }
    __syncthreads();
    if (tid == 0) {
        float cdsum = 0.f;
#pragma unroll
        for (int t = 0; t < GZT; ++t) cdsum += ts[t];
        float l1num = 0.f; int msum = 0;
#pragma unroll
        for (int bb = 0; bb < BB; ++bb) { l1num += g_l1part[bb]; msum += g_cnt[bb]; }
        float l1 = l1num / 3.0f / (float)msum;
        float cd = cdsum / (float)BB;
        out[0] = l1 + expf(-l1) * cd;
        g_done = 0;                      // reset for next graph replay
    }
}

// ---------------------------------------------------------------------------
extern "C" void kernel_launch(void* const* d_in, const int* in_sizes, int n_in,
                              void* d_out, int out_size) {
    const float* pred   = (const float*)d_in[0];
    const float* target = (const float*)d_in[1];
    const int*   mask   = (const int*)  d_in[2];
    const float* points = (const float*)d_in[3];
    float* out = (float*)d_out;

    prep_kernel<<<16, 1024>>>(pred, target, mask, points);

    dim3 grid(CHQ, GZT);                 // (16, 16) = 256 blocks
    chamfer_kernel<<<grid, 256>>>(out);
}